// round 7
// baseline (speedup 1.0000x reference)
#include <cuda_runtime.h>
#include <math.h>
#include <stdint.h>

#define L   4096
#define H   768
#define NH  12
#define HD  64

// Projected Q, K, V (tf32-rounded fp32): [3][L][H]. Static device scratch.
__device__ float g_QKV[3][L * H];

// ===========================================================================
// helpers
// ===========================================================================
__device__ __forceinline__ uint32_t smem_u32(const void* p) {
    uint32_t a;
    asm("{ .reg .u64 t; cvta.to.shared.u64 t, %1; cvt.u32.u64 %0, t; }" : "=r"(a) : "l"(p));
    return a;
}

// m16n8k8 tf32 mma. A row-major 16x8, B col-major 8x8, C/D f32.
__device__ __forceinline__ void mma_tf32(float c[4],
                                         uint32_t a0, uint32_t a1, uint32_t a2, uint32_t a3,
                                         uint32_t b0, uint32_t b1) {
    asm volatile(
        "mma.sync.aligned.m16n8k8.row.col.f32.tf32.tf32.f32 "
        "{%0,%1,%2,%3}, {%4,%5,%6,%7}, {%8,%9}, {%0,%1,%2,%3};"
        : "+f"(c[0]), "+f"(c[1]), "+f"(c[2]), "+f"(c[3])
        : "r"(a0), "r"(a1), "r"(a2), "r"(a3), "r"(b0), "r"(b1));
}

// ldmatrix x4 (b16 view). On 32-bit data, each 8x4-float matrix lands as the
// tf32 fragment pattern: lane(g,t) <- M[g][t].
__device__ __forceinline__ void ldsm4(uint32_t& r0, uint32_t& r1, uint32_t& r2, uint32_t& r3,
                                      uint32_t addr) {
    asm volatile("ldmatrix.sync.aligned.m8n8.x4.shared.b16 {%0,%1,%2,%3}, [%4];"
                 : "=r"(r0), "=r"(r1), "=r"(r2), "=r"(r3) : "r"(addr));
}

__device__ __forceinline__ uint32_t cvt_tf32(float x) {   // RNA round, valid fp32 bits
    uint32_t u; asm("cvt.rna.tf32.f32 %0, %1;" : "=r"(u) : "f"(x)); return u;
}

#define CP16(dst, src) \
    asm volatile("cp.async.cg.shared.global [%0], [%1], 16;" :: "r"(dst), "l"(src))
#define CP_COMMIT()  asm volatile("cp.async.commit_group;")
#define CP_WAIT0()   asm volatile("cp.async.wait_group 0;")
#define CP_WAIT1()   asm volatile("cp.async.wait_group 1;")

// exp(x) for x <= 0 with NO MUFU: 2^(x*log2e) via magic-number round + deg-5 poly.
__device__ __forceinline__ float expfast(float x) {
    x = fmaxf(x, -80.0f);
    const float L2E   = 1.4426950408889634f;
    const float MAGIC = 12582912.0f;            // 1.5 * 2^23
    float tt = fmaf(x, L2E, MAGIC);
    int   ji = __float_as_int(tt) << 23;
    float jf = tt - MAGIC;
    float f  = fmaf(x, L2E, -jf);
    float p  = 1.3333558146e-3f;
    p = fmaf(p, f, 9.6181291076e-3f);
    p = fmaf(p, f, 5.5504108664e-2f);
    p = fmaf(p, f, 2.4022650696e-1f);
    p = fmaf(p, f, 6.9314718056e-1f);
    p = fmaf(p, f, 1.0f);
    return __int_as_float(__float_as_int(p) + ji);
}

// ===========================================================================
// Kernel 1: QKV projection, mma.sync tf32, 3xTF32 split, ldmatrix frag loads.
// (unchanged from round 6)
// ===========================================================================
#define P_AS(buf) ((buf) * 4608)           // [128][36] floats
#define P_BS(buf) (9216 + (buf) * 4608)
#define PROJ_SMEM_B (18432 * 4)            // 73728 bytes

__global__ __launch_bounds__(256, 2) void qkv_proj_tc(
    const float* __restrict__ Xq, const float* __restrict__ Xk, const float* __restrict__ Xv,
    const float* __restrict__ Wq, const float* __restrict__ Wk, const float* __restrict__ Wv,
    const float* __restrict__ bq, const float* __restrict__ bk, const float* __restrict__ bv)
{
    extern __shared__ float sm[];
    const uint32_t smb = smem_u32(sm);

    const int tid  = threadIdx.x;
    const int w    = tid >> 5, lane = tid & 31;
    const int g    = lane >> 2, t = lane & 3;
    const int wm   = w & 3, wn = w >> 2;
    const int z    = blockIdx.z;
    const int n0   = blockIdx.x * 128;
    const int m0   = blockIdx.y * 128;

    const float* X    = (z == 0) ? Xq : (z == 1) ? Xk : Xv;
    const float* W    = (z == 0) ? Wq : (z == 1) ? Wk : Wv;
    const float* bias = (z == 0) ? bq : (z == 1) ? bk : bv;
    float* Y = g_QKV[z];

    const int lr8 = lane & 7;
    const uint32_t a_row  = (uint32_t)(32 * wm + ((lane >> 3) & 1) * 8 + lr8);
    const uint32_t a_byte = (uint32_t)(((lane >> 4) & 1) * 16);
    const uint32_t b_row  = (uint32_t)(64 * wn + ((lane >> 4) & 1) * 8 + lr8);
    const uint32_t b_byte = (uint32_t)(((lane >> 3) & 1) * 16);

    float acc[2][8][4];
    #pragma unroll
    for (int mt = 0; mt < 2; mt++)
        #pragma unroll
        for (int nt = 0; nt < 8; nt++)
            #pragma unroll
            for (int j = 0; j < 4; j++) acc[mt][nt][j] = 0.f;

    auto load_tile = [&](int kt, int buf) {
        #pragma unroll
        for (int i = 0; i < 4; i++) {
            int id = tid + i * 256;
            int r  = id >> 3;
            int c  = (id & 7) * 4;
            CP16(smb + (P_AS(buf) + r * 36 + c) * 4,
                 X + (size_t)(m0 + r) * H + kt * 32 + c);
            CP16(smb + (P_BS(buf) + r * 36 + c) * 4,
                 W + (size_t)(n0 + r) * H + kt * 32 + c);
        }
    };

    load_tile(0, 0);
    CP_COMMIT();

    #pragma unroll 1
    for (int kt = 0; kt < 24; kt++) {
        const int buf = kt & 1;
        if (kt < 23) { load_tile(kt + 1, buf ^ 1); CP_COMMIT(); CP_WAIT1(); }
        else         { CP_WAIT0(); }
        __syncthreads();

        const uint32_t ald = smb + (P_AS(buf) + a_row * 36) * 4 + a_byte;
        const uint32_t bld = smb + (P_BS(buf) + b_row * 36) * 4 + b_byte;

        #pragma unroll
        for (int ks = 0; ks < 4; ks++) {
            uint32_t ab[2][4], asml[2][4];
            #pragma unroll
            for (int mt = 0; mt < 2; mt++) {
                uint32_t r0, r1, r2, r3;
                ldsm4(r0, r1, r2, r3, ald + (uint32_t)(mt * 16 * 36 * 4 + ks * 32));
                float f0 = __uint_as_float(r0), f1 = __uint_as_float(r1);
                float f2 = __uint_as_float(r2), f3 = __uint_as_float(r3);
                ab[mt][0] = cvt_tf32(f0); asml[mt][0] = cvt_tf32(f0 - __uint_as_float(ab[mt][0]));
                ab[mt][1] = cvt_tf32(f1); asml[mt][1] = cvt_tf32(f1 - __uint_as_float(ab[mt][1]));
                ab[mt][2] = cvt_tf32(f2); asml[mt][2] = cvt_tf32(f2 - __uint_as_float(ab[mt][2]));
                ab[mt][3] = cvt_tf32(f3); asml[mt][3] = cvt_tf32(f3 - __uint_as_float(ab[mt][3]));
            }
            #pragma unroll
            for (int j = 0; j < 4; j++) {
                uint32_t r0, r1, r2, r3;
                ldsm4(r0, r1, r2, r3, bld + (uint32_t)(j * 16 * 36 * 4 + ks * 32));
                float f0 = __uint_as_float(r0), f1 = __uint_as_float(r1);
                float f2 = __uint_as_float(r2), f3 = __uint_as_float(r3);
                uint32_t bb0 = cvt_tf32(f0), bs0 = cvt_tf32(f0 - __uint_as_float(bb0));
                uint32_t bb1 = cvt_tf32(f1), bs1 = cvt_tf32(f1 - __uint_as_float(bb1));
                uint32_t bb2 = cvt_tf32(f2), bs2 = cvt_tf32(f2 - __uint_as_float(bb2));
                uint32_t bb3 = cvt_tf32(f3), bs3 = cvt_tf32(f3 - __uint_as_float(bb3));
                #pragma unroll
                for (int mt = 0; mt < 2; mt++) {
                    mma_tf32(acc[mt][2*j],   ab[mt][0], ab[mt][1], ab[mt][2], ab[mt][3], bb0, bb1);
                    mma_tf32(acc[mt][2*j],   ab[mt][0], ab[mt][1], ab[mt][2], ab[mt][3], bs0, bs1);
                    mma_tf32(acc[mt][2*j],   asml[mt][0], asml[mt][1], asml[mt][2], asml[mt][3], bb0, bb1);
                    mma_tf32(acc[mt][2*j+1], ab[mt][0], ab[mt][1], ab[mt][2], ab[mt][3], bb2, bb3);
                    mma_tf32(acc[mt][2*j+1], ab[mt][0], ab[mt][1], ab[mt][2], ab[mt][3], bs2, bs3);
                    mma_tf32(acc[mt][2*j+1], asml[mt][0], asml[mt][1], asml[mt][2], asml[mt][3], bb2, bb3);
                }
            }
        }
        __syncthreads();
    }

    #pragma unroll
    for (int mt = 0; mt < 2; mt++) {
        int row = m0 + 32 * wm + 16 * mt + g;
        #pragma unroll
        for (int nt = 0; nt < 8; nt++) {
            int col = n0 + 64 * wn + 8 * nt + 2 * t;
            float2 bv2 = *(const float2*)&bias[col];
            float2 y0, y1;
            y0.x = __uint_as_float(cvt_tf32(acc[mt][nt][0] + bv2.x));
            y0.y = __uint_as_float(cvt_tf32(acc[mt][nt][1] + bv2.y));
            y1.x = __uint_as_float(cvt_tf32(acc[mt][nt][2] + bv2.x));
            y1.y = __uint_as_float(cvt_tf32(acc[mt][nt][3] + bv2.y));
            *(float2*)&Y[(size_t)row * H + col]       = y0;
            *(float2*)&Y[(size_t)(row + 8) * H + col] = y1;
        }
    }
}

// ===========================================================================
// Kernel 2: flash attention, mma.sync tf32 + ldmatrix.
// NEW SHAPE: 128 threads / 4 warps / Br=64, 3 CTAs/SM (reg cap 170 -> ILP+TLP).
// Per-warp algorithm identical to round 6 (16 q-rows, Bc=64).
// smem floats: Ms 2x64 @0 | Ks 2x[64][68] @128 | VsT [64][68] @8832 | Ps [64][68] @13184
// total 17536 floats = 70144 B  (x3 CTAs = 210 KB <= 228 KB)
// ===========================================================================
#define F_MS(buf)  ((buf) * 64)
#define F_KS(buf)  (128 + (buf) * 4352)
#define F_VT       8832
#define F_PS       13184
#define FLASH_SMEM_B (17536 * 4)           // 70144 bytes
#define NIT        (L / 64)                // 64

__global__ __launch_bounds__(128, 3) void flash_attn_tc(
    const float* __restrict__ mask,
    float* __restrict__ out)
{
    extern __shared__ float sm[];
    const uint32_t smb = smem_u32(sm);

    const int tid  = threadIdx.x;
    const int w    = tid >> 5, lane = tid & 31;
    const int g    = lane >> 2, t = lane & 3;
    const int h    = blockIdx.y;
    const int q0   = blockIdx.x * 64;
    const int hc   = h * HD;

    const float* Qg = g_QKV[0];
    const float* Kg = g_QKV[1];
    const float* Vg = g_QKV[2];

    // Q A-fragments, register resident (values already tf32).
    uint32_t qa[8][4];
    {
        const float* q0p = Qg + (size_t)(q0 + 16 * w + g) * H + hc;
        const float* q1p = q0p + 8 * H;
        #pragma unroll
        for (int kk = 0; kk < 8; kk++) {
            qa[kk][0] = __float_as_uint(q0p[8 * kk + t]);
            qa[kk][1] = __float_as_uint(q1p[8 * kk + t]);
            qa[kk][2] = __float_as_uint(q0p[8 * kk + t + 4]);
            qa[kk][3] = __float_as_uint(q1p[8 * kk + t + 4]);
        }
    }

    // ldmatrix lane addressing
    const int lr8 = lane & 7;
    const uint32_t kv_row  = (uint32_t)(((lane >> 4) & 1) * 8 + lr8);
    const uint32_t kv_byte = (uint32_t)(((lane >> 3) & 1) * 16);
    const uint32_t p_row   = (uint32_t)(((lane >> 3) & 1) * 8 + lr8);
    const uint32_t p_byte  = (uint32_t)(((lane >> 4) & 1) * 16);

    const uint32_t kld0 = smb + (F_KS(0) + kv_row * 68) * 4 + kv_byte;
    const uint32_t kld1 = smb + (F_KS(1) + kv_row * 68) * 4 + kv_byte;
    const uint32_t vld  = smb + (F_VT   + kv_row * 68) * 4 + kv_byte;
    const uint32_t pld  = smb + (F_PS + (16 * w + (int)p_row) * 68) * 4 + p_byte;

    // V transpose mapping: warp pair -> kv half (w&1), d half (w>>1); lane -> kv.
    // Each thread owns 32 V floats: kv=vkv, d in [vd0, vd0+32).
    const int vkv = (w & 1) * 32 + lane;
    const int vd0 = (w >> 1) * 32;
    const float* vbase = Vg + (size_t)vkv * H + hc + vd0;

    float o[8][4];
    #pragma unroll
    for (int nt = 0; nt < 8; nt++)
        #pragma unroll
        for (int j = 0; j < 4; j++) o[nt][j] = 0.f;
    float m0 = -INFINITY, m1 = -INFINITY, l0 = 0.f, l1 = 0.f;

    auto load_k = [&](int it, int buf) {
        const int k0 = it * 64;
        #pragma unroll
        for (int i = 0; i < 8; i++) {
            int id = tid + i * 128;          // 0..1023
            int r  = id >> 4;
            int c  = (id & 15) * 4;
            CP16(smb + (F_KS(buf) + r * 68 + c) * 4, Kg + (size_t)(k0 + r) * H + hc + c);
        }
        if (tid < 16) CP16(smb + (F_MS(buf) + tid * 4) * 4, mask + k0 + tid * 4);
    };

    load_k(0, 0);
    CP_COMMIT();

    float4 vp[8];
    #pragma unroll
    for (int j = 0; j < 8; j++) vp[j] = *(const float4*)(vbase + 4 * j);

    float* Psw = sm + F_PS + (16 * w) * 68;

    #pragma unroll 1
    for (int it = 0; it < NIT; it++) {
        const int buf = it & 1;
        CP_WAIT0();
        __syncthreads();   // K(it) visible; prev iter's compute done (VsT, Ks(buf^1) free)

        // Store prefetched V(it) transposed: VsT[d][kv]
        #pragma unroll
        for (int j = 0; j < 8; j++) {
            sm[F_VT + (vd0 + 4 * j + 0) * 68 + vkv] = vp[j].x;
            sm[F_VT + (vd0 + 4 * j + 1) * 68 + vkv] = vp[j].y;
            sm[F_VT + (vd0 + 4 * j + 2) * 68 + vkv] = vp[j].z;
            sm[F_VT + (vd0 + 4 * j + 3) * 68 + vkv] = vp[j].w;
        }
        if (it + 1 < NIT) {
            load_k(it + 1, buf ^ 1);
            CP_COMMIT();
        }
        __syncthreads();   // VsT ready

        const uint32_t kld = buf ? kld1 : kld0;
        const float* Ms = sm + F_MS(buf);

        // ---- S = Q K^T ----
        float s[8][4];
        #pragma unroll
        for (int nt = 0; nt < 8; nt++)
            #pragma unroll
            for (int j = 0; j < 4; j++) s[nt][j] = 0.f;

        #pragma unroll
        for (int kk = 0; kk < 8; kk++) {
            #pragma unroll
            for (int j = 0; j < 4; j++) {
                uint32_t k0r, k1r, k2r, k3r;
                ldsm4(k0r, k1r, k2r, k3r, kld + (uint32_t)(j * 16 * 68 * 4 + kk * 32));
                mma_tf32(s[2*j],   qa[kk][0], qa[kk][1], qa[kk][2], qa[kk][3], k0r, k1r);
                mma_tf32(s[2*j+1], qa[kk][0], qa[kk][1], qa[kk][2], qa[kk][3], k2r, k3r);
            }
        }

        // Prefetch V(it+1): LDG latency hidden behind softmax, short liveness.
        if (it + 1 < NIT) {
            const float* vptr = vbase + (size_t)(it + 1) * 64 * H;
            #pragma unroll
            for (int j = 0; j < 8; j++) vp[j] = *(const float4*)(vptr + 4 * j);
        }

        // ---- scale + mask, online softmax ----
        float rmx0 = -INFINITY, rmx1 = -INFINITY;
        #pragma unroll
        for (int nt = 0; nt < 8; nt++) {
            float2 mk = *(const float2*)&Ms[8 * nt + 2 * t];
            s[nt][0] = fmaf(s[nt][0], 0.125f, mk.x);
            s[nt][1] = fmaf(s[nt][1], 0.125f, mk.y);
            s[nt][2] = fmaf(s[nt][2], 0.125f, mk.x);
            s[nt][3] = fmaf(s[nt][3], 0.125f, mk.y);
            rmx0 = fmaxf(rmx0, fmaxf(s[nt][0], s[nt][1]));
            rmx1 = fmaxf(rmx1, fmaxf(s[nt][2], s[nt][3]));
        }
        rmx0 = fmaxf(rmx0, __shfl_xor_sync(0xffffffffu, rmx0, 1));
        rmx0 = fmaxf(rmx0, __shfl_xor_sync(0xffffffffu, rmx0, 2));
        rmx1 = fmaxf(rmx1, __shfl_xor_sync(0xffffffffu, rmx1, 1));
        rmx1 = fmaxf(rmx1, __shfl_xor_sync(0xffffffffu, rmx1, 2));

        float mn0 = fmaxf(m0, rmx0), mn1 = fmaxf(m1, rmx1);
        float al0 = expfast(m0 - mn0), al1 = expfast(m1 - mn1);
        m0 = mn0; m1 = mn1;

        float rs0 = 0.f, rs1 = 0.f;
        #pragma unroll
        for (int nt = 0; nt < 8; nt++) {
            float p0 = expfast(s[nt][0] - mn0);
            float p1 = expfast(s[nt][1] - mn0);
            float p2 = expfast(s[nt][2] - mn1);
            float p3 = expfast(s[nt][3] - mn1);
            rs0 += p0 + p1;
            rs1 += p2 + p3;
            float2 v0, v1;
            v0.x = __uint_as_float(cvt_tf32(p0));
            v0.y = __uint_as_float(cvt_tf32(p1));
            v1.x = __uint_as_float(cvt_tf32(p2));
            v1.y = __uint_as_float(cvt_tf32(p3));
            *(float2*)&Psw[g * 68 + 8 * nt + 2 * t]       = v0;
            *(float2*)&Psw[(g + 8) * 68 + 8 * nt + 2 * t] = v1;
        }
        rs0 += __shfl_xor_sync(0xffffffffu, rs0, 1);
        rs0 += __shfl_xor_sync(0xffffffffu, rs0, 2);
        rs1 += __shfl_xor_sync(0xffffffffu, rs1, 1);
        rs1 += __shfl_xor_sync(0xffffffffu, rs1, 2);
        l0 = l0 * al0 + rs0;
        l1 = l1 * al1 + rs1;

        #pragma unroll
        for (int nt = 0; nt < 8; nt++) {
            o[nt][0] *= al0; o[nt][1] *= al0;
            o[nt][2] *= al1; o[nt][3] *= al1;
        }
        __syncwarp();

        // ---- O += P V ----
        #pragma unroll
        for (int kk = 0; kk < 8; kk++) {
            uint32_t pa0, pa1, pa2, pa3;
            ldsm4(pa0, pa1, pa2, pa3, pld + (uint32_t)(kk * 32));
            #pragma unroll
            for (int j = 0; j < 4; j++) {
                uint32_t v0r, v1r, v2r, v3r;
                ldsm4(v0r, v1r, v2r, v3r, vld + (uint32_t)(j * 16 * 68 * 4 + kk * 32));
                mma_tf32(o[2*j],   pa0, pa1, pa2, pa3, v0r, v1r);
                mma_tf32(o[2*j+1], pa0, pa1, pa2, pa3, v2r, v3r);
            }
        }
    }

    // ---- epilogue ----
    const float inv0 = 1.0f / l0, inv1 = 1.0f / l1;
    const int row = q0 + 16 * w + g;
    #pragma unroll
    for (int nt = 0; nt < 8; nt++) {
        int col = hc + 8 * nt + 2 * t;
        float2 r0, r1;
        r0.x = o[nt][0] * inv0; r0.y = o[nt][1] * inv0;
        r1.x = o[nt][2] * inv1; r1.y = o[nt][3] * inv1;
        *(float2*)&out[(size_t)row * H + col]       = r0;
        *(float2*)&out[(size_t)(row + 8) * H + col] = r1;
    }
}

// ---------------------------------------------------------------------------
extern "C" void kernel_launch(void* const* d_in, const int* in_sizes, int n_in,
                              void* d_out, int out_size)
{
    const float* query = (const float*)d_in[0];
    const float* key   = (const float*)d_in[1];
    const float* value = (const float*)d_in[2];
    const float* mask  = (const float*)d_in[3];
    const float* Wq    = (const float*)d_in[4];
    const float* bq    = (const float*)d_in[5];
    const float* Wk    = (const float*)d_in[6];
    const float* bk    = (const float*)d_in[7];
    const float* Wv    = (const float*)d_in[8];
    const float* bv    = (const float*)d_in[9];
    float* out = (float*)d_out;

    cudaFuncSetAttribute(qkv_proj_tc,   cudaFuncAttributeMaxDynamicSharedMemorySize, PROJ_SMEM_B);
    cudaFuncSetAttribute(flash_attn_tc, cudaFuncAttributeMaxDynamicSharedMemorySize, FLASH_SMEM_B);

    dim3 pg(H / 128, L / 128, 3);    // 6 x 32 x 3
    qkv_proj_tc<<<pg, 256, PROJ_SMEM_B>>>(query, key, value, Wq, Wk, Wv, bq, bk, bv);

    dim3 ag(L / 64, NH);             // 64 x 12 = 768 CTAs
    flash_attn_tc<<<ag, 128, FLASH_SMEM_B>>>(mask, out);
}

// round 8
// speedup vs baseline: 1.7198x; 1.7198x over previous
#include <cuda_runtime.h>
#include <cuda_fp16.h>
#include <math.h>
#include <stdint.h>

#define L   4096
#define H   768
#define NH  12
#define HD  64

// Projected Q, K, V, fp16: [3][L*H]. Static device scratch (~18.9 MB).
__device__ __half g_QKV[3][L * H];

// ===========================================================================
// helpers
// ===========================================================================
__device__ __forceinline__ uint32_t smem_u32(const void* p) {
    uint32_t a;
    asm("{ .reg .u64 t; cvta.to.shared.u64 t, %1; cvt.u32.u64 %0, t; }" : "=r"(a) : "l"(p));
    return a;
}

// fp16 mma m16n8k16, fp32 accum. A row-major 16x16, B col-major 16x8.
__device__ __forceinline__ void mma_f16(float c[4],
                                        uint32_t a0, uint32_t a1, uint32_t a2, uint32_t a3,
                                        uint32_t b0, uint32_t b1) {
    asm volatile(
        "mma.sync.aligned.m16n8k16.row.col.f32.f16.f16.f32 "
        "{%0,%1,%2,%3}, {%4,%5,%6,%7}, {%8,%9}, {%0,%1,%2,%3};"
        : "+f"(c[0]), "+f"(c[1]), "+f"(c[2]), "+f"(c[3])
        : "r"(a0), "r"(a1), "r"(a2), "r"(a3), "r"(b0), "r"(b1));
}

// tf32 mma m16n8k8 (projection kernel only).
__device__ __forceinline__ void mma_tf32(float c[4],
                                         uint32_t a0, uint32_t a1, uint32_t a2, uint32_t a3,
                                         uint32_t b0, uint32_t b1) {
    asm volatile(
        "mma.sync.aligned.m16n8k8.row.col.f32.tf32.tf32.f32 "
        "{%0,%1,%2,%3}, {%4,%5,%6,%7}, {%8,%9}, {%0,%1,%2,%3};"
        : "+f"(c[0]), "+f"(c[1]), "+f"(c[2]), "+f"(c[3])
        : "r"(a0), "r"(a1), "r"(a2), "r"(a3), "r"(b0), "r"(b1));
}

__device__ __forceinline__ void ldsm4(uint32_t& r0, uint32_t& r1, uint32_t& r2, uint32_t& r3,
                                      uint32_t addr) {
    asm volatile("ldmatrix.sync.aligned.m8n8.x4.shared.b16 {%0,%1,%2,%3}, [%4];"
                 : "=r"(r0), "=r"(r1), "=r"(r2), "=r"(r3) : "r"(addr));
}
__device__ __forceinline__ void ldsm4t(uint32_t& r0, uint32_t& r1, uint32_t& r2, uint32_t& r3,
                                       uint32_t addr) {
    asm volatile("ldmatrix.sync.aligned.m8n8.x4.trans.shared.b16 {%0,%1,%2,%3}, [%4];"
                 : "=r"(r0), "=r"(r1), "=r"(r2), "=r"(r3) : "r"(addr));
}

__device__ __forceinline__ uint32_t cvt_tf32(float x) {
    uint32_t u; asm("cvt.rna.tf32.f32 %0, %1;" : "=r"(u) : "f"(x)); return u;
}

#define CP16(dst, src) \
    asm volatile("cp.async.cg.shared.global [%0], [%1], 16;" :: "r"(dst), "l"(src))
#define CP_COMMIT()  asm volatile("cp.async.commit_group;")
#define CP_WAIT0()   asm volatile("cp.async.wait_group 0;")
#define CP_WAIT1()   asm volatile("cp.async.wait_group 1;")

// exp(x) for x <= 0 with NO MUFU.
__device__ __forceinline__ float expfast(float x) {
    x = fmaxf(x, -80.0f);
    const float L2E   = 1.4426950408889634f;
    const float MAGIC = 12582912.0f;            // 1.5 * 2^23
    float tt = fmaf(x, L2E, MAGIC);
    int   ji = __float_as_int(tt) << 23;
    float jf = tt - MAGIC;
    float f  = fmaf(x, L2E, -jf);
    float p  = 1.3333558146e-3f;
    p = fmaf(p, f, 9.6181291076e-3f);
    p = fmaf(p, f, 5.5504108664e-2f);
    p = fmaf(p, f, 2.4022650696e-1f);
    p = fmaf(p, f, 6.9314718056e-1f);
    p = fmaf(p, f, 1.0f);
    return __int_as_float(__float_as_int(p) + ji);
}

// ===========================================================================
// Kernel 1: QKV projection, tf32 3x-split mma (fp32-accurate), fp16 output.
// Same structure as round 6 winner; only the store dtype changed.
// ===========================================================================
#define P_AS(buf) ((buf) * 4608)           // [128][36] floats
#define P_BS(buf) (9216 + (buf) * 4608)
#define PROJ_SMEM_B (18432 * 4)            // 73728 bytes

__global__ __launch_bounds__(256, 2) void qkv_proj_tc(
    const float* __restrict__ Xq, const float* __restrict__ Xk, const float* __restrict__ Xv,
    const float* __restrict__ Wq, const float* __restrict__ Wk, const float* __restrict__ Wv,
    const float* __restrict__ bq, const float* __restrict__ bk, const float* __restrict__ bv)
{
    extern __shared__ float sm[];
    const uint32_t smb = smem_u32(sm);

    const int tid  = threadIdx.x;
    const int w    = tid >> 5, lane = tid & 31;
    const int g    = lane >> 2, t = lane & 3;
    const int wm   = w & 3, wn = w >> 2;
    const int z    = blockIdx.z;
    const int n0   = blockIdx.x * 128;
    const int m0   = blockIdx.y * 128;

    const float* X    = (z == 0) ? Xq : (z == 1) ? Xk : Xv;
    const float* W    = (z == 0) ? Wq : (z == 1) ? Wk : Wv;
    const float* bias = (z == 0) ? bq : (z == 1) ? bk : bv;
    __half* Y = g_QKV[z];

    const int lr8 = lane & 7;
    const uint32_t a_row  = (uint32_t)(32 * wm + ((lane >> 3) & 1) * 8 + lr8);
    const uint32_t a_byte = (uint32_t)(((lane >> 4) & 1) * 16);
    const uint32_t b_row  = (uint32_t)(64 * wn + ((lane >> 4) & 1) * 8 + lr8);
    const uint32_t b_byte = (uint32_t)(((lane >> 3) & 1) * 16);

    float acc[2][8][4];
    #pragma unroll
    for (int mt = 0; mt < 2; mt++)
        #pragma unroll
        for (int nt = 0; nt < 8; nt++)
            #pragma unroll
            for (int j = 0; j < 4; j++) acc[mt][nt][j] = 0.f;

    auto load_tile = [&](int kt, int buf) {
        #pragma unroll
        for (int i = 0; i < 4; i++) {
            int id = tid + i * 256;
            int r  = id >> 3;
            int c  = (id & 7) * 4;
            CP16(smb + (P_AS(buf) + r * 36 + c) * 4,
                 X + (size_t)(m0 + r) * H + kt * 32 + c);
            CP16(smb + (P_BS(buf) + r * 36 + c) * 4,
                 W + (size_t)(n0 + r) * H + kt * 32 + c);
        }
    };

    load_tile(0, 0);
    CP_COMMIT();

    #pragma unroll 1
    for (int kt = 0; kt < 24; kt++) {
        const int buf = kt & 1;
        if (kt < 23) { load_tile(kt + 1, buf ^ 1); CP_COMMIT(); CP_WAIT1(); }
        else         { CP_WAIT0(); }
        __syncthreads();

        const uint32_t ald = smb + (P_AS(buf) + a_row * 36) * 4 + a_byte;
        const uint32_t bld = smb + (P_BS(buf) + b_row * 36) * 4 + b_byte;

        #pragma unroll
        for (int ks = 0; ks < 4; ks++) {
            uint32_t ab[2][4], asml[2][4];
            #pragma unroll
            for (int mt = 0; mt < 2; mt++) {
                uint32_t r0, r1, r2, r3;
                ldsm4(r0, r1, r2, r3, ald + (uint32_t)(mt * 16 * 36 * 4 + ks * 32));
                float f0 = __uint_as_float(r0), f1 = __uint_as_float(r1);
                float f2 = __uint_as_float(r2), f3 = __uint_as_float(r3);
                ab[mt][0] = cvt_tf32(f0); asml[mt][0] = cvt_tf32(f0 - __uint_as_float(ab[mt][0]));
                ab[mt][1] = cvt_tf32(f1); asml[mt][1] = cvt_tf32(f1 - __uint_as_float(ab[mt][1]));
                ab[mt][2] = cvt_tf32(f2); asml[mt][2] = cvt_tf32(f2 - __uint_as_float(ab[mt][2]));
                ab[mt][3] = cvt_tf32(f3); asml[mt][3] = cvt_tf32(f3 - __uint_as_float(ab[mt][3]));
            }
            #pragma unroll
            for (int j = 0; j < 4; j++) {
                uint32_t r0, r1, r2, r3;
                ldsm4(r0, r1, r2, r3, bld + (uint32_t)(j * 16 * 36 * 4 + ks * 32));
                float f0 = __uint_as_float(r0), f1 = __uint_as_float(r1);
                float f2 = __uint_as_float(r2), f3 = __uint_as_float(r3);
                uint32_t bb0 = cvt_tf32(f0), bs0 = cvt_tf32(f0 - __uint_as_float(bb0));
                uint32_t bb1 = cvt_tf32(f1), bs1 = cvt_tf32(f1 - __uint_as_float(bb1));
                uint32_t bb2 = cvt_tf32(f2), bs2 = cvt_tf32(f2 - __uint_as_float(bb2));
                uint32_t bb3 = cvt_tf32(f3), bs3 = cvt_tf32(f3 - __uint_as_float(bb3));
                #pragma unroll
                for (int mt = 0; mt < 2; mt++) {
                    mma_tf32(acc[mt][2*j],   ab[mt][0], ab[mt][1], ab[mt][2], ab[mt][3], bb0, bb1);
                    mma_tf32(acc[mt][2*j],   ab[mt][0], ab[mt][1], ab[mt][2], ab[mt][3], bs0, bs1);
                    mma_tf32(acc[mt][2*j],   asml[mt][0], asml[mt][1], asml[mt][2], asml[mt][3], bb0, bb1);
                    mma_tf32(acc[mt][2*j+1], ab[mt][0], ab[mt][1], ab[mt][2], ab[mt][3], bb2, bb3);
                    mma_tf32(acc[mt][2*j+1], ab[mt][0], ab[mt][1], ab[mt][2], ab[mt][3], bs2, bs3);
                    mma_tf32(acc[mt][2*j+1], asml[mt][0], asml[mt][1], asml[mt][2], asml[mt][3], bb2, bb3);
                }
            }
        }
        __syncthreads();
    }

    // Epilogue: +bias, round to fp16, store.
    #pragma unroll
    for (int mt = 0; mt < 2; mt++) {
        int row = m0 + 32 * wm + 16 * mt + g;
        #pragma unroll
        for (int nt = 0; nt < 8; nt++) {
            int col = n0 + 64 * wn + 8 * nt + 2 * t;
            float2 bv2 = *(const float2*)&bias[col];
            __half2 y0 = __floats2half2_rn(acc[mt][nt][0] + bv2.x, acc[mt][nt][1] + bv2.y);
            __half2 y1 = __floats2half2_rn(acc[mt][nt][2] + bv2.x, acc[mt][nt][3] + bv2.y);
            *(__half2*)&Y[(size_t)row * H + col]       = y0;
            *(__half2*)&Y[(size_t)(row + 8) * H + col] = y1;
        }
    }
}

// ===========================================================================
// Kernel 2: flash attention, fp16 mma m16n8k16.
// 256 thr / 8 warps / Br=128 (warp w: rows [16w,16w+16)), Bc=64, 2 CTAs/SM.
// K,V both cp.async double-buffered as fp16; V frags via ldmatrix.trans;
// P stays in registers (C-frag layout == A-frag layout).
// smem bytes: Ms 2x64 f32 @0 (512B) | Ks 2x[64][72] half @512 | Vs 2x... @18944
// total 37376 B.
// ===========================================================================
#define MS_OFF(buf) ((buf) * 256)
#define KS_OFF(buf) (512 + (buf) * 9216)
#define VS_OFF(buf) (18944 + (buf) * 9216)
#define FLASH_SMEM_B 37376
#define NIT (L / 64)                      // 64

__global__ __launch_bounds__(256, 2) void flash_attn_tc(
    const float* __restrict__ mask,
    float* __restrict__ out)
{
    extern __shared__ char smc[];
    const uint32_t smb = smem_u32(smc);

    const int tid  = threadIdx.x;
    const int w    = tid >> 5, lane = tid & 31;
    const int g    = lane >> 2, t = lane & 3;
    const int h    = blockIdx.y;
    const int q0   = blockIdx.x * 128;
    const int hc   = h * HD;

    const __half* Qg = g_QKV[0];
    const __half* Kg = g_QKV[1];
    const __half* Vg = g_QKV[2];

    // Q A-fragments (m16n8k16): qa[kk][0..3] for k-blocks of 16.
    uint32_t qa[4][4];
    {
        const __half* qp = Qg + (size_t)(q0 + 16 * w + g) * H + hc;
        #pragma unroll
        for (int kk = 0; kk < 4; kk++) {
            qa[kk][0] = *(const uint32_t*)(qp + 16 * kk + 2 * t);
            qa[kk][1] = *(const uint32_t*)(qp + 8 * H + 16 * kk + 2 * t);
            qa[kk][2] = *(const uint32_t*)(qp + 16 * kk + 8 + 2 * t);
            qa[kk][3] = *(const uint32_t*)(qp + 8 * H + 16 * kk + 8 + 2 * t);
        }
    }

    // ldmatrix lane addressing: lanes 0-15 -> 16 rows; lanes 16-31 -> +16B col.
    const uint32_t lrow = (uint32_t)(lane & 15);
    const uint32_t lcol = (uint32_t)((lane >> 4) * 16);
    const uint32_t kb0 = smb + KS_OFF(0) + lrow * 144 + lcol;
    const uint32_t kb1 = smb + KS_OFF(1) + lrow * 144 + lcol;
    const uint32_t vb0 = smb + VS_OFF(0) + lrow * 144 + lcol;
    const uint32_t vb1 = smb + VS_OFF(1) + lrow * 144 + lcol;

    float o[8][4];
    #pragma unroll
    for (int nt = 0; nt < 8; nt++)
        #pragma unroll
        for (int j = 0; j < 4; j++) o[nt][j] = 0.f;
    float m0 = -INFINITY, m1 = -INFINITY, l0 = 0.f, l1 = 0.f;

    auto load_kv = [&](int it, int buf) {
        const int k0 = it * 64;
        #pragma unroll
        for (int i = 0; i < 2; i++) {
            int id = tid + i * 256;        // 0..511
            int r  = id >> 3;              // 0..63
            int c  = (id & 7) * 8;         // halfs
            CP16(smb + KS_OFF(buf) + r * 144 + c * 2, Kg + (size_t)(k0 + r) * H + hc + c);
            CP16(smb + VS_OFF(buf) + r * 144 + c * 2, Vg + (size_t)(k0 + r) * H + hc + c);
        }
        if (tid < 16) CP16(smb + MS_OFF(buf) + tid * 16, mask + k0 + tid * 4);
    };

    load_kv(0, 0);
    CP_COMMIT();

    #pragma unroll 1
    for (int it = 0; it < NIT; it++) {
        const int buf = it & 1;
        CP_WAIT0();
        __syncthreads();   // tile(it) visible; all warps done with buf^1

        if (it + 1 < NIT) { load_kv(it + 1, buf ^ 1); CP_COMMIT(); }

        const uint32_t kld = buf ? kb1 : kb0;
        const uint32_t vld = buf ? vb1 : vb0;
        const float* Ms = (const float*)(smc + MS_OFF(buf));

        // ---- S = Q K^T (16 x 64 per warp) ----
        float s[8][4];
        #pragma unroll
        for (int nt = 0; nt < 8; nt++)
            #pragma unroll
            for (int j = 0; j < 4; j++) s[nt][j] = 0.f;

        #pragma unroll
        for (int kk = 0; kk < 4; kk++) {
            #pragma unroll
            for (int j = 0; j < 4; j++) {
                uint32_t k0r, k1r, k2r, k3r;
                ldsm4(k0r, k1r, k2r, k3r, kld + (uint32_t)(j * 2304 + kk * 32));
                mma_f16(s[2*j],   qa[kk][0], qa[kk][1], qa[kk][2], qa[kk][3], k0r, k2r);
                mma_f16(s[2*j+1], qa[kk][0], qa[kk][1], qa[kk][2], qa[kk][3], k1r, k3r);
            }
        }

        // ---- scale + mask, online softmax ----
        float rmx0 = -INFINITY, rmx1 = -INFINITY;
        #pragma unroll
        for (int nt = 0; nt < 8; nt++) {
            float2 mk = *(const float2*)&Ms[8 * nt + 2 * t];
            s[nt][0] = fmaf(s[nt][0], 0.125f, mk.x);
            s[nt][1] = fmaf(s[nt][1], 0.125f, mk.y);
            s[nt][2] = fmaf(s[nt][2], 0.125f, mk.x);
            s[nt][3] = fmaf(s[nt][3], 0.125f, mk.y);
            rmx0 = fmaxf(rmx0, fmaxf(s[nt][0], s[nt][1]));
            rmx1 = fmaxf(rmx1, fmaxf(s[nt][2], s[nt][3]));
        }
        rmx0 = fmaxf(rmx0, __shfl_xor_sync(0xffffffffu, rmx0, 1));
        rmx0 = fmaxf(rmx0, __shfl_xor_sync(0xffffffffu, rmx0, 2));
        rmx1 = fmaxf(rmx1, __shfl_xor_sync(0xffffffffu, rmx1, 1));
        rmx1 = fmaxf(rmx1, __shfl_xor_sync(0xffffffffu, rmx1, 2));

        float mn0 = fmaxf(m0, rmx0), mn1 = fmaxf(m1, rmx1);
        float al0 = expfast(m0 - mn0), al1 = expfast(m1 - mn1);
        m0 = mn0; m1 = mn1;

        // P in registers, packed directly as fp16 A-fragments.
        uint32_t pa[4][4];
        float rs0 = 0.f, rs1 = 0.f;
        #pragma unroll
        for (int nt = 0; nt < 8; nt++) {
            float p0 = expfast(s[nt][0] - mn0);
            float p1 = expfast(s[nt][1] - mn0);
            float p2 = expfast(s[nt][2] - mn1);
            float p3 = expfast(s[nt][3] - mn1);
            rs0 += p0 + p1;
            rs1 += p2 + p3;
            __half2 h01 = __floats2half2_rn(p0, p1);
            __half2 h23 = __floats2half2_rn(p2, p3);
            pa[nt >> 1][(nt & 1) * 2 + 0] = *(uint32_t*)&h01;
            pa[nt >> 1][(nt & 1) * 2 + 1] = *(uint32_t*)&h23;
        }
        rs0 += __shfl_xor_sync(0xffffffffu, rs0, 1);
        rs0 += __shfl_xor_sync(0xffffffffu, rs0, 2);
        rs1 += __shfl_xor_sync(0xffffffffu, rs1, 1);
        rs1 += __shfl_xor_sync(0xffffffffu, rs1, 2);
        l0 = l0 * al0 + rs0;
        l1 = l1 * al1 + rs1;

        #pragma unroll
        for (int nt = 0; nt < 8; nt++) {
            o[nt][0] *= al0; o[nt][1] *= al0;
            o[nt][2] *= al1; o[nt][3] *= al1;
        }

        // ---- O += P V : V B-frags via ldmatrix.trans on row-major V ----
        #pragma unroll
        for (int kk = 0; kk < 4; kk++) {
            #pragma unroll
            for (int j = 0; j < 4; j++) {
                uint32_t v0r, v1r, v2r, v3r;
                ldsm4t(v0r, v1r, v2r, v3r, vld + (uint32_t)(kk * 2304 + j * 32));
                mma_f16(o[2*j],   pa[kk][0], pa[kk][1], pa[kk][2], pa[kk][3], v0r, v1r);
                mma_f16(o[2*j+1], pa[kk][0], pa[kk][1], pa[kk][2], pa[kk][3], v2r, v3r);
            }
        }
    }

    // ---- epilogue ----
    const float inv0 = 1.0f / l0, inv1 = 1.0f / l1;
    const int row = q0 + 16 * w + g;
    #pragma unroll
    for (int nt = 0; nt < 8; nt++) {
        int col = hc + 8 * nt + 2 * t;
        float2 r0, r1;
        r0.x = o[nt][0] * inv0; r0.y = o[nt][1] * inv0;
        r1.x = o[nt][2] * inv1; r1.y = o[nt][3] * inv1;
        *(float2*)&out[(size_t)row * H + col]       = r0;
        *(float2*)&out[(size_t)(row + 8) * H + col] = r1;
    }
}

// ---------------------------------------------------------------------------
extern "C" void kernel_launch(void* const* d_in, const int* in_sizes, int n_in,
                              void* d_out, int out_size)
{
    const float* query = (const float*)d_in[0];
    const float* key   = (const float*)d_in[1];
    const float* value = (const float*)d_in[2];
    const float* mask  = (const float*)d_in[3];
    const float* Wq    = (const float*)d_in[4];
    const float* bq    = (const float*)d_in[5];
    const float* Wk    = (const float*)d_in[6];
    const float* bk    = (const float*)d_in[7];
    const float* Wv    = (const float*)d_in[8];
    const float* bv    = (const float*)d_in[9];
    float* out = (float*)d_out;

    cudaFuncSetAttribute(qkv_proj_tc,   cudaFuncAttributeMaxDynamicSharedMemorySize, PROJ_SMEM_B);
    cudaFuncSetAttribute(flash_attn_tc, cudaFuncAttributeMaxDynamicSharedMemorySize, FLASH_SMEM_B);

    dim3 pg(H / 128, L / 128, 3);    // 6 x 32 x 3
    qkv_proj_tc<<<pg, 256, PROJ_SMEM_B>>>(query, key, value, Wq, Wk, Wv, bq, bk, bv);

    dim3 ag(L / 128, NH);            // 32 x 12
    flash_attn_tc<<<ag, 256, FLASH_SMEM_B>>>(mask, out);
}

// round 9
// speedup vs baseline: 2.0354x; 1.1836x over previous
#include <cuda_runtime.h>
#include <cuda_fp16.h>
#include <math.h>
#include <stdint.h>

#define L   4096
#define H   768
#define NH  12
#define HD  64

// Projected Q, K, V, fp16: [3][L*H]. Static device scratch.
__device__ __half g_QKV[3][L * H];
// fp16 hi/lo splits of inputs (X) and weights (W) for double-fp16 projection.
__device__ __half g_Xh[3][L * H], g_Xl[3][L * H];
__device__ __half g_Wh[3][H * H], g_Wl[3][H * H];

// ===========================================================================
// helpers
// ===========================================================================
__device__ __forceinline__ uint32_t smem_u32(const void* p) {
    uint32_t a;
    asm("{ .reg .u64 t; cvta.to.shared.u64 t, %1; cvt.u32.u64 %0, t; }" : "=r"(a) : "l"(p));
    return a;
}

// fp16 mma m16n8k16, fp32 accum. A row-major 16x16, B col-major 16x8.
__device__ __forceinline__ void mma_f16(float c[4],
                                        uint32_t a0, uint32_t a1, uint32_t a2, uint32_t a3,
                                        uint32_t b0, uint32_t b1) {
    asm volatile(
        "mma.sync.aligned.m16n8k16.row.col.f32.f16.f16.f32 "
        "{%0,%1,%2,%3}, {%4,%5,%6,%7}, {%8,%9}, {%0,%1,%2,%3};"
        : "+f"(c[0]), "+f"(c[1]), "+f"(c[2]), "+f"(c[3])
        : "r"(a0), "r"(a1), "r"(a2), "r"(a3), "r"(b0), "r"(b1));
}

__device__ __forceinline__ void ldsm4(uint32_t& r0, uint32_t& r1, uint32_t& r2, uint32_t& r3,
                                      uint32_t addr) {
    asm volatile("ldmatrix.sync.aligned.m8n8.x4.shared.b16 {%0,%1,%2,%3}, [%4];"
                 : "=r"(r0), "=r"(r1), "=r"(r2), "=r"(r3) : "r"(addr));
}
__device__ __forceinline__ void ldsm4t(uint32_t& r0, uint32_t& r1, uint32_t& r2, uint32_t& r3,
                                       uint32_t addr) {
    asm volatile("ldmatrix.sync.aligned.m8n8.x4.trans.shared.b16 {%0,%1,%2,%3}, [%4];"
                 : "=r"(r0), "=r"(r1), "=r"(r2), "=r"(r3) : "r"(addr));
}

#define CP16(dst, src) \
    asm volatile("cp.async.cg.shared.global [%0], [%1], 16;" :: "r"(dst), "l"(src))
#define CP_COMMIT()  asm volatile("cp.async.commit_group;")
#define CP_WAIT0()   asm volatile("cp.async.wait_group 0;")
#define CP_WAIT1()   asm volatile("cp.async.wait_group 1;")

// exp(x) for x <= 0 with NO MUFU.
__device__ __forceinline__ float expfast(float x) {
    x = fmaxf(x, -80.0f);
    const float L2E   = 1.4426950408889634f;
    const float MAGIC = 12582912.0f;            // 1.5 * 2^23
    float tt = fmaf(x, L2E, MAGIC);
    int   ji = __float_as_int(tt) << 23;
    float jf = tt - MAGIC;
    float f  = fmaf(x, L2E, -jf);
    float p  = 1.3333558146e-3f;
    p = fmaf(p, f, 9.6181291076e-3f);
    p = fmaf(p, f, 5.5504108664e-2f);
    p = fmaf(p, f, 2.4022650696e-1f);
    p = fmaf(p, f, 6.9314718056e-1f);
    p = fmaf(p, f, 1.0f);
    return __int_as_float(__float_as_int(p) + ji);
}

// ===========================================================================
// Kernel 0: fp32 -> (fp16 hi, fp16 lo) split prepass.
// ===========================================================================
__global__ __launch_bounds__(256) void split_prep(const float* __restrict__ src,
                                                  int which, int isW, int n)
{
    __half* hi = isW ? g_Wh[which] : g_Xh[which];
    __half* lo = isW ? g_Wl[which] : g_Xl[which];
    int i = (blockIdx.x * blockDim.x + threadIdx.x) * 4;
    if (i >= n) return;
    float4 v = *(const float4*)(src + i);
    __half hx = __float2half_rn(v.x), hy = __float2half_rn(v.y);
    __half hz = __float2half_rn(v.z), hw = __float2half_rn(v.w);
    __half lx = __float2half_rn(v.x - __half2float(hx));
    __half ly = __float2half_rn(v.y - __half2float(hy));
    __half lz = __float2half_rn(v.z - __half2float(hz));
    __half lw = __float2half_rn(v.w - __half2float(hw));
    *(__half2*)(hi + i)     = __halves2half2(hx, hy);
    *(__half2*)(hi + i + 2) = __halves2half2(hz, hw);
    *(__half2*)(lo + i)     = __halves2half2(lx, ly);
    *(__half2*)(lo + i + 2) = __halves2half2(lz, lw);
}

// ===========================================================================
// Kernel 1: QKV projection, double-fp16 mma m16n8k16 (fp32-class accuracy).
// Tile 128x128, BK=32, 8 warps (wm=w&3: 32 rows, wn=w>>2: 64 cols).
// smem per buffer (halfs): Ah[128][40] Al Bh Bl (stride 40 -> ldsm conflict-free).
// ===========================================================================
#define PJ_ST 40                            // halfs per row
#define PJ_AH(buf) ((uint32_t)(buf) * 40960u + 0u)       // byte offsets
#define PJ_AL(buf) ((uint32_t)(buf) * 40960u + 10240u)
#define PJ_BH(buf) ((uint32_t)(buf) * 40960u + 20480u)
#define PJ_BL(buf) ((uint32_t)(buf) * 40960u + 30720u)
#define PROJ_SMEM_B 81920

__global__ __launch_bounds__(256, 2) void qkv_proj_tc(
    const float* __restrict__ bq, const float* __restrict__ bk, const float* __restrict__ bv)
{
    extern __shared__ char smc[];
    const uint32_t smb = smem_u32(smc);

    const int tid  = threadIdx.x;
    const int w    = tid >> 5, lane = tid & 31;
    const int g    = lane >> 2, t = lane & 3;
    const int wm   = w & 3, wn = w >> 2;
    const int z    = blockIdx.z;
    const int n0   = blockIdx.x * 128;
    const int m0   = blockIdx.y * 128;

    const __half* Xh = g_Xh[z];
    const __half* Xl = g_Xl[z];
    const __half* Wh = g_Wh[z];
    const __half* Wl = g_Wl[z];
    const float* bias = (z == 0) ? bq : (z == 1) ? bk : bv;
    __half* Y = g_QKV[z];

    // ldsm lane addressing (b16 x4): lanes 0-15 -> 16 rows; 16-31 -> +16B col.
    const uint32_t lrow = (uint32_t)(lane & 15);
    const uint32_t lcol = (uint32_t)((lane >> 4) * 16);

    float acc[2][8][4];
    #pragma unroll
    for (int mt = 0; mt < 2; mt++)
        #pragma unroll
        for (int nt = 0; nt < 8; nt++)
            #pragma unroll
            for (int j = 0; j < 4; j++) acc[mt][nt][j] = 0.f;

    auto load_tile = [&](int kt, int buf) {
        // 4 arrays x 128 rows x 4 chunks(16B) = 2048 chunks; 8 per thread.
        #pragma unroll
        for (int i = 0; i < 8; i++) {
            int c   = tid + i * 256;
            int arr = i >> 1;                 // 0:Ah 1:Al 2:Bh 3:Bl (c>>9)
            int wi  = c & 511;
            int r   = wi >> 2;
            int kc  = (wi & 3) * 8;           // halfs
            const __half* src =
                (arr == 0) ? Xh + (size_t)(m0 + r) * H + kt * 32 + kc :
                (arr == 1) ? Xl + (size_t)(m0 + r) * H + kt * 32 + kc :
                (arr == 2) ? Wh + (size_t)(n0 + r) * H + kt * 32 + kc :
                             Wl + (size_t)(n0 + r) * H + kt * 32 + kc;
            uint32_t off = (arr == 0) ? PJ_AH(buf) : (arr == 1) ? PJ_AL(buf)
                         : (arr == 2) ? PJ_BH(buf) : PJ_BL(buf);
            CP16(smb + off + (uint32_t)(r * PJ_ST + kc) * 2, src);
        }
    };

    load_tile(0, 0);
    CP_COMMIT();

    #pragma unroll 1
    for (int kt = 0; kt < 24; kt++) {
        const int buf = kt & 1;
        if (kt < 23) { load_tile(kt + 1, buf ^ 1); CP_COMMIT(); CP_WAIT1(); }
        else         { CP_WAIT0(); }
        __syncthreads();

        const uint32_t ahb = smb + PJ_AH(buf) + (32 * wm + lrow) * (PJ_ST * 2) + lcol;
        const uint32_t alb = smb + PJ_AL(buf) + (32 * wm + lrow) * (PJ_ST * 2) + lcol;
        const uint32_t bhb = smb + PJ_BH(buf) + (64 * wn + lrow) * (PJ_ST * 2) + lcol;
        const uint32_t blb = smb + PJ_BL(buf) + (64 * wn + lrow) * (PJ_ST * 2) + lcol;

        #pragma unroll
        for (int ks = 0; ks < 2; ks++) {
            uint32_t ah[2][4], al[2][4];
            #pragma unroll
            for (int mt = 0; mt < 2; mt++) {
                ldsm4(ah[mt][0], ah[mt][1], ah[mt][2], ah[mt][3],
                      ahb + (uint32_t)(mt * 16 * PJ_ST * 2 + ks * 32));
                ldsm4(al[mt][0], al[mt][1], al[mt][2], al[mt][3],
                      alb + (uint32_t)(mt * 16 * PJ_ST * 2 + ks * 32));
            }
            #pragma unroll
            for (int jb = 0; jb < 4; jb++) {
                uint32_t bh0, bh1, bh2, bh3, bl0, bl1, bl2, bl3;
                ldsm4(bh0, bh1, bh2, bh3, bhb + (uint32_t)(jb * 16 * PJ_ST * 2 + ks * 32));
                ldsm4(bl0, bl1, bl2, bl3, blb + (uint32_t)(jb * 16 * PJ_ST * 2 + ks * 32));
                #pragma unroll
                for (int mt = 0; mt < 2; mt++) {
                    mma_f16(acc[mt][2*jb],   ah[mt][0], ah[mt][1], ah[mt][2], ah[mt][3], bh0, bh2);
                    mma_f16(acc[mt][2*jb],   ah[mt][0], ah[mt][1], ah[mt][2], ah[mt][3], bl0, bl2);
                    mma_f16(acc[mt][2*jb],   al[mt][0], al[mt][1], al[mt][2], al[mt][3], bh0, bh2);
                    mma_f16(acc[mt][2*jb+1], ah[mt][0], ah[mt][1], ah[mt][2], ah[mt][3], bh1, bh3);
                    mma_f16(acc[mt][2*jb+1], ah[mt][0], ah[mt][1], ah[mt][2], ah[mt][3], bl1, bl3);
                    mma_f16(acc[mt][2*jb+1], al[mt][0], al[mt][1], al[mt][2], al[mt][3], bh1, bh3);
                }
            }
        }
        __syncthreads();
    }

    // Epilogue: +bias, round to fp16, store.
    #pragma unroll
    for (int mt = 0; mt < 2; mt++) {
        int row = m0 + 32 * wm + 16 * mt + g;
        #pragma unroll
        for (int nt = 0; nt < 8; nt++) {
            int col = n0 + 64 * wn + 8 * nt + 2 * t;
            float2 bv2 = *(const float2*)&bias[col];
            __half2 y0 = __floats2half2_rn(acc[mt][nt][0] + bv2.x, acc[mt][nt][1] + bv2.y);
            __half2 y1 = __floats2half2_rn(acc[mt][nt][2] + bv2.x, acc[mt][nt][3] + bv2.y);
            *(__half2*)&Y[(size_t)row * H + col]       = y0;
            *(__half2*)&Y[(size_t)(row + 8) * H + col] = y1;
        }
    }
}

// ===========================================================================
// Kernel 2: flash attention, fp16 mma m16n8k16 (UNCHANGED from round 8).
// ===========================================================================
#define MS_OFF(buf) ((buf) * 256)
#define KS_OFF(buf) (512 + (buf) * 9216)
#define VS_OFF(buf) (18944 + (buf) * 9216)
#define FLASH_SMEM_B 37376
#define NIT (L / 64)                      // 64

__global__ __launch_bounds__(256, 2) void flash_attn_tc(
    const float* __restrict__ mask,
    float* __restrict__ out)
{
    extern __shared__ char smc[];
    const uint32_t smb = smem_u32(smc);

    const int tid  = threadIdx.x;
    const int w    = tid >> 5, lane = tid & 31;
    const int g    = lane >> 2, t = lane & 3;
    const int h    = blockIdx.y;
    const int q0   = blockIdx.x * 128;
    const int hc   = h * HD;

    const __half* Qg = g_QKV[0];
    const __half* Kg = g_QKV[1];
    const __half* Vg = g_QKV[2];

    uint32_t qa[4][4];
    {
        const __half* qp = Qg + (size_t)(q0 + 16 * w + g) * H + hc;
        #pragma unroll
        for (int kk = 0; kk < 4; kk++) {
            qa[kk][0] = *(const uint32_t*)(qp + 16 * kk + 2 * t);
            qa[kk][1] = *(const uint32_t*)(qp + 8 * H + 16 * kk + 2 * t);
            qa[kk][2] = *(const uint32_t*)(qp + 16 * kk + 8 + 2 * t);
            qa[kk][3] = *(const uint32_t*)(qp + 8 * H + 16 * kk + 8 + 2 * t);
        }
    }

    const uint32_t lrow = (uint32_t)(lane & 15);
    const uint32_t lcol = (uint32_t)((lane >> 4) * 16);
    const uint32_t kb0 = smb + KS_OFF(0) + lrow * 144 + lcol;
    const uint32_t kb1 = smb + KS_OFF(1) + lrow * 144 + lcol;
    const uint32_t vb0 = smb + VS_OFF(0) + lrow * 144 + lcol;
    const uint32_t vb1 = smb + VS_OFF(1) + lrow * 144 + lcol;

    float o[8][4];
    #pragma unroll
    for (int nt = 0; nt < 8; nt++)
        #pragma unroll
        for (int j = 0; j < 4; j++) o[nt][j] = 0.f;
    float m0 = -INFINITY, m1 = -INFINITY, l0 = 0.f, l1 = 0.f;

    auto load_kv = [&](int it, int buf) {
        const int k0 = it * 64;
        #pragma unroll
        for (int i = 0; i < 2; i++) {
            int id = tid + i * 256;
            int r  = id >> 3;
            int c  = (id & 7) * 8;
            CP16(smb + KS_OFF(buf) + r * 144 + c * 2, Kg + (size_t)(k0 + r) * H + hc + c);
            CP16(smb + VS_OFF(buf) + r * 144 + c * 2, Vg + (size_t)(k0 + r) * H + hc + c);
        }
        if (tid < 16) CP16(smb + MS_OFF(buf) + tid * 16, mask + k0 + tid * 4);
    };

    load_kv(0, 0);
    CP_COMMIT();

    #pragma unroll 1
    for (int it = 0; it < NIT; it++) {
        const int buf = it & 1;
        CP_WAIT0();
        __syncthreads();

        if (it + 1 < NIT) { load_kv(it + 1, buf ^ 1); CP_COMMIT(); }

        const uint32_t kld = buf ? kb1 : kb0;
        const uint32_t vld = buf ? vb1 : vb0;
        const float* Ms = (const float*)(smc + MS_OFF(buf));

        float s[8][4];
        #pragma unroll
        for (int nt = 0; nt < 8; nt++)
            #pragma unroll
            for (int j = 0; j < 4; j++) s[nt][j] = 0.f;

        #pragma unroll
        for (int kk = 0; kk < 4; kk++) {
            #pragma unroll
            for (int j = 0; j < 4; j++) {
                uint32_t k0r, k1r, k2r, k3r;
                ldsm4(k0r, k1r, k2r, k3r, kld + (uint32_t)(j * 2304 + kk * 32));
                mma_f16(s[2*j],   qa[kk][0], qa[kk][1], qa[kk][2], qa[kk][3], k0r, k2r);
                mma_f16(s[2*j+1], qa[kk][0], qa[kk][1], qa[kk][2], qa[kk][3], k1r, k3r);
            }
        }

        float rmx0 = -INFINITY, rmx1 = -INFINITY;
        #pragma unroll
        for (int nt = 0; nt < 8; nt++) {
            float2 mk = *(const float2*)&Ms[8 * nt + 2 * t];
            s[nt][0] = fmaf(s[nt][0], 0.125f, mk.x);
            s[nt][1] = fmaf(s[nt][1], 0.125f, mk.y);
            s[nt][2] = fmaf(s[nt][2], 0.125f, mk.x);
            s[nt][3] = fmaf(s[nt][3], 0.125f, mk.y);
            rmx0 = fmaxf(rmx0, fmaxf(s[nt][0], s[nt][1]));
            rmx1 = fmaxf(rmx1, fmaxf(s[nt][2], s[nt][3]));
        }
        rmx0 = fmaxf(rmx0, __shfl_xor_sync(0xffffffffu, rmx0, 1));
        rmx0 = fmaxf(rmx0, __shfl_xor_sync(0xffffffffu, rmx0, 2));
        rmx1 = fmaxf(rmx1, __shfl_xor_sync(0xffffffffu, rmx1, 1));
        rmx1 = fmaxf(rmx1, __shfl_xor_sync(0xffffffffu, rmx1, 2));

        float mn0 = fmaxf(m0, rmx0), mn1 = fmaxf(m1, rmx1);
        float al0 = expfast(m0 - mn0), al1 = expfast(m1 - mn1);
        m0 = mn0; m1 = mn1;

        uint32_t pa[4][4];
        float rs0 = 0.f, rs1 = 0.f;
        #pragma unroll
        for (int nt = 0; nt < 8; nt++) {
            float p0 = expfast(s[nt][0] - mn0);
            float p1 = expfast(s[nt][1] - mn0);
            float p2 = expfast(s[nt][2] - mn1);
            float p3 = expfast(s[nt][3] - mn1);
            rs0 += p0 + p1;
            rs1 += p2 + p3;
            __half2 h01 = __floats2half2_rn(p0, p1);
            __half2 h23 = __floats2half2_rn(p2, p3);
            pa[nt >> 1][(nt & 1) * 2 + 0] = *(uint32_t*)&h01;
            pa[nt >> 1][(nt & 1) * 2 + 1] = *(uint32_t*)&h23;
        }
        rs0 += __shfl_xor_sync(0xffffffffu, rs0, 1);
        rs0 += __shfl_xor_sync(0xffffffffu, rs0, 2);
        rs1 += __shfl_xor_sync(0xffffffffu, rs1, 1);
        rs1 += __shfl_xor_sync(0xffffffffu, rs1, 2);
        l0 = l0 * al0 + rs0;
        l1 = l1 * al1 + rs1;

        #pragma unroll
        for (int nt = 0; nt < 8; nt++) {
            o[nt][0] *= al0; o[nt][1] *= al0;
            o[nt][2] *= al1; o[nt][3] *= al1;
        }

        #pragma unroll
        for (int kk = 0; kk < 4; kk++) {
            #pragma unroll
            for (int j = 0; j < 4; j++) {
                uint32_t v0r, v1r, v2r, v3r;
                ldsm4t(v0r, v1r, v2r, v3r, vld + (uint32_t)(kk * 2304 + j * 32));
                mma_f16(o[2*j],   pa[kk][0], pa[kk][1], pa[kk][2], pa[kk][3], v0r, v1r);
                mma_f16(o[2*j+1], pa[kk][0], pa[kk][1], pa[kk][2], pa[kk][3], v2r, v3r);
            }
        }
    }

    const float inv0 = 1.0f / l0, inv1 = 1.0f / l1;
    const int row = q0 + 16 * w + g;
    #pragma unroll
    for (int nt = 0; nt < 8; nt++) {
        int col = hc + 8 * nt + 2 * t;
        float2 r0, r1;
        r0.x = o[nt][0] * inv0; r0.y = o[nt][1] * inv0;
        r1.x = o[nt][2] * inv1; r1.y = o[nt][3] * inv1;
        *(float2*)&out[(size_t)row * H + col]       = r0;
        *(float2*)&out[(size_t)(row + 8) * H + col] = r1;
    }
}

// ---------------------------------------------------------------------------
extern "C" void kernel_launch(void* const* d_in, const int* in_sizes, int n_in,
                              void* d_out, int out_size)
{
    const float* query = (const float*)d_in[0];
    const float* key   = (const float*)d_in[1];
    const float* value = (const float*)d_in[2];
    const float* mask  = (const float*)d_in[3];
    const float* Wq    = (const float*)d_in[4];
    const float* bq    = (const float*)d_in[5];
    const float* Wk    = (const float*)d_in[6];
    const float* bk    = (const float*)d_in[7];
    const float* Wv    = (const float*)d_in[8];
    const float* bv    = (const float*)d_in[9];
    float* out = (float*)d_out;

    cudaFuncSetAttribute(qkv_proj_tc,   cudaFuncAttributeMaxDynamicSharedMemorySize, PROJ_SMEM_B);
    cudaFuncSetAttribute(flash_attn_tc, cudaFuncAttributeMaxDynamicSharedMemorySize, FLASH_SMEM_B);

    const int nX = L * H, nW = H * H;
    split_prep<<<(nX / 4 + 255) / 256, 256>>>(query, 0, 0, nX);
    split_prep<<<(nX / 4 + 255) / 256, 256>>>(key,   1, 0, nX);
    split_prep<<<(nX / 4 + 255) / 256, 256>>>(value, 2, 0, nX);
    split_prep<<<(nW / 4 + 255) / 256, 256>>>(Wq, 0, 1, nW);
    split_prep<<<(nW / 4 + 255) / 256, 256>>>(Wk, 1, 1, nW);
    split_prep<<<(nW / 4 + 255) / 256, 256>>>(Wv, 2, 1, nW);

    dim3 pg(H / 128, L / 128, 3);    // 6 x 32 x 3
    qkv_proj_tc<<<pg, 256, PROJ_SMEM_B>>>(bq, bk, bv);

    dim3 ag(L / 128, NH);            // 32 x 12
    flash_attn_tc<<<ag, 256, FLASH_SMEM_B>>>(mask, out);
}